// round 7
// baseline (speedup 1.0000x reference)
#include <cuda_runtime.h>
#include <cuda_bf16.h>

// ---------------------------------------------------------------------------
// Model_2 : FC -> graph conv (threshold adjacency) -> conv1d x3 -> FC -> logsoftmax
// B=64, N=750, F=8, NF=250
// ---------------------------------------------------------------------------

#define INV_BN 0.9999950000374997f   // 1/sqrt(1 + 1e-5)
#define GN 750

typedef unsigned long long ull;

// Scratch (device globals; no dynamic allocation allowed)
__device__ float g_xcat[64 * 1000];          // concat [s(250) | g(750)] per batch
__device__ float g_pool1[64 * 32 * 500];     // after conv1+bn+relu+pool
__device__ float g_pool2[64 * 64 * 250];     // after conv2+bn+relu+pool
__device__ float g_part3[500 * 64 * 128];    // conv3 K-split partials [ks][b][oc]

// ---- packed f32x2 helpers (sm_100+ : 2x fp32 FMA throughput) ----------------
__device__ __forceinline__ ull pk2(float lo, float hi) {
    ull r;
    asm("mov.b64 %0, {%1,%2};" : "=l"(r) : "f"(lo), "f"(hi));
    return r;
}
__device__ __forceinline__ ull fma2(ull a, ull b, ull c) {
    ull d;
    asm("fma.rn.f32x2 %0, %1, %2, %3;" : "=l"(d) : "l"(a), "l"(b), "l"(c));
    return d;
}
__device__ __forceinline__ float2 upk2(ull v) {
    float2 r;
    asm("mov.b64 {%0,%1}, %2;" : "=f"(r.x), "=f"(r.y) : "l"(v));
    return r;
}

// ---------------------------------------------------------------------------
// K_front: blocks 0..63 -> graph conv per batch; blocks 64..127 -> linear1.
// Graph: hybrid bitonic sort (regs + shfl for j<32, smem for j>=32) + exact
// interval search + prefix sums. (diff*diff < 0.01f) is monotone in |diff| in
// fp32 -> adjacency = contiguous interval in sorted order; binary search with
// the IDENTICAL predicate reproduces the exact reference edge set.
// ---------------------------------------------------------------------------
__global__ void __launch_bounds__(1024) k_front(
        const float* __restrict__ xs, const float* __restrict__ W1,
        const float* __restrict__ b1, const float* __restrict__ gl,
        const float* __restrict__ bl,
        const float* __restrict__ xg, const float* __restrict__ Wg,
        const float* __restrict__ bg, const float* __restrict__ g1,
        const float* __restrict__ be1) {
    int t = threadIdx.x;
    __shared__ float sd[1024];
    __shared__ int   si[1024];
    __shared__ float pre[751 * 8];
    __shared__ float wsum[32][8];
    __shared__ float wgs[64];

    if (blockIdx.x >= 64) {
        // ------- linear1 path -------
        int b = blockIdx.x - 64;
        if (t < 250) sd[t] = xs[b * 250 + t];
        __syncthreads();
        if (t < 250) {
            float acc = 0.f;
            #pragma unroll 5
            for (int k = 0; k < 250; k++) acc = fmaf(sd[k], W1[k * 250 + t], acc);
            float v = (acc + b1[t]) * (INV_BN * gl[t]) + bl[t];
            g_xcat[b * 1000 + t] = fmaxf(v, 0.f);
        }
        return;
    }

    // ------- graph path -------
    int b = blockIdx.x;
    float key;
    int   pay;
    if (t < GN) { key = xg[b * 6000 + t * 8]; pay = t; }
    else        { key = __int_as_float(0x7f800000); pay = -1; }
    if (t < 64) wgs[t] = Wg[t];

    // hybrid bitonic sort ascending, 1 element per thread
    for (int k2 = 2; k2 <= 1024; k2 <<= 1) {
        bool up = ((t & k2) == 0);
        for (int j = k2 >> 1; j > 0; j >>= 1) {
            float kq; int pq;
            if (j >= 32) {
                __syncthreads();
                sd[t] = key; si[t] = pay;
                __syncthreads();
                kq = sd[t ^ j]; pq = si[t ^ j];
            } else {
                kq = __shfl_xor_sync(0xffffffffu, key, j);
                pq = __shfl_xor_sync(0xffffffffu, pay, j);
            }
            bool lower = (t & j) == 0;
            float a = lower ? key : kq;   // value at lower index
            float c = lower ? kq : key;   // value at upper index
            bool sw = up ? (a > c) : (a < c);   // strict, matches reference ties
            if (sw) { key = kq; pay = pq; }
        }
    }
    __syncthreads();
    sd[t] = key; si[t] = pay;
    __syncthreads();

    float dn = 0.f;
    int lo = 0, hi = 0;
    float y[8];
    if (t < GN) {
        float dsv = key;
        int L = 0, R = t;
        while (L < R) { int m = (L + R) >> 1; float df = dsv - sd[m];
                        if (df * df < 0.01f) R = m; else L = m + 1; }
        lo = L;
        L = t + 1; R = GN;
        while (L < R) { int m = (L + R) >> 1; float df = dsv - sd[m];
                        if (df * df < 0.01f) L = m + 1; else R = m; }
        hi = L;
        dn = rsqrtf((float)(hi - lo));
        int orig = pay;
        const float4* xp = reinterpret_cast<const float4*>(xg + (size_t)b * 6000 + orig * 8);
        float4 a4 = xp[0], c4 = xp[1];
        float xv[8] = {a4.x, a4.y, a4.z, a4.w, c4.x, c4.y, c4.z, c4.w};
        #pragma unroll
        for (int f = 0; f < 8; f++) {
            float s = 0.f;
            #pragma unroll
            for (int fp = 0; fp < 8; fp++) s = fmaf(xv[fp], wgs[fp * 8 + f], s);
            y[f] = s * dn;
        }
    } else {
        #pragma unroll
        for (int f = 0; f < 8; f++) y[f] = 0.f;
    }

    int lane = t & 31, wrp = t >> 5;
    #pragma unroll
    for (int f = 0; f < 8; f++) {
        float v = y[f];
        #pragma unroll
        for (int d = 1; d < 32; d <<= 1) {
            float o = __shfl_up_sync(0xffffffffu, v, d);
            if (lane >= d) v += o;
        }
        y[f] = v;
    }
    if (lane == 31) {
        #pragma unroll
        for (int f = 0; f < 8; f++) wsum[wrp][f] = y[f];
    }
    __syncthreads();
    if (t < 8) {
        float run = 0.f;
        for (int w = 0; w < 32; w++) { float x = wsum[w][t]; wsum[w][t] = run; run += x; }
    }
    __syncthreads();
    if (t < GN) {
        #pragma unroll
        for (int f = 0; f < 8; f++) pre[(t + 1) * 8 + f] = y[f] + wsum[wrp][f];
    }
    if (t < 8) pre[t] = 0.f;
    __syncthreads();

    if (t < GN) {
        float sc = INV_BN * g1[0], sh = be1[0];
        float gsum = 0.f;
        #pragma unroll
        for (int f = 0; f < 8; f++) {
            float s = pre[hi * 8 + f] - pre[lo * 8 + f];
            float hv = fmaf(dn, s, bg[f]);
            hv = fmaf(hv, sc, sh);
            gsum += fmaxf(hv, 0.f);
        }
        g_xcat[b * 1000 + 250 + pay] = gsum * 0.125f;
    }
}

// ---------------------------------------------------------------------------
// K3: conv1 (1->32, k=5, pad=2) + bn + relu + maxpool2 : [64,1,1000] -> [64,32,500]
// grid (64, 4): pooled tile of 125
// ---------------------------------------------------------------------------
__global__ void k_conv1(const float* __restrict__ Wc1, const float* __restrict__ bc1,
                        const float* __restrict__ gc1, const float* __restrict__ bec1) {
    int b = blockIdx.x, pt = blockIdx.y;
    int p0 = pt * 125;
    __shared__ float xs2[256];
    __shared__ float w[160], bb[32], gg[32], be[32];
    int t = threadIdx.x;
    for (int m = t; m < 254; m += 256) {
        int q = 2 * p0 - 2 + m;
        xs2[m] = (q >= 0 && q < 1000) ? g_xcat[b * 1000 + q] : 0.f;
    }
    if (t < 160) w[t] = Wc1[t];
    if (t < 32) { bb[t] = bc1[t]; gg[t] = gc1[t] * INV_BN; be[t] = bec1[t]; }
    __syncthreads();
    for (int idx = t; idx < 32 * 125; idx += 256) {
        int c = idx / 125, p = idx - c * 125;
        int m = 2 * p;
        float v0 = bb[c], v1 = bb[c];
        #pragma unroll
        for (int k = 0; k < 5; k++) {
            float wk = w[c * 5 + k];
            v0 = fmaf(xs2[m + k],     wk, v0);
            v1 = fmaf(xs2[m + 1 + k], wk, v1);
        }
        v0 = fmaf(v0, gg[c], be[c]);
        v1 = fmaf(v1, gg[c], be[c]);
        g_pool1[(b * 32 + c) * 500 + p0 + p] = fmaxf(fmaxf(v0, v1), 0.f);
    }
}

// ---------------------------------------------------------------------------
// K4: conv2 (32->64, k=5, pad=2) + bn + relu + maxpool2 : [64,32,500] -> [64,64,250]
// grid (b=64, pt=4 (64 pooled), oh=2 (32 oc)), 64 threads.
// f32x2 lanes = adjacent conv positions (the maxpool pair), even/odd phase
// pair arrays (no duplication). Thread tile: 4 oc x 8 pooled.
// ---------------------------------------------------------------------------
__global__ void __launch_bounds__(64) k_conv2(
        const float* __restrict__ Wc2, const float* __restrict__ bc2,
        const float* __restrict__ gc2, const float* __restrict__ bec2) {
    int b = blockIdx.x, pt = blockIdx.y, oh = blockIdx.z;
    int p0 = pt * 64;            // pooled start
    int oc0 = oh * 32;
    __shared__ float swt[160][33];                 // [ic*5+k][oc_local], padded
    __shared__ __align__(16) float2 sxe[8][66];    // ic-chunk of 8
    __shared__ __align__(16) float2 sxo[8][66];
    int t = threadIdx.x;
    int ocg = t & 7;             // oc_local base = 4*ocg
    int pg  = t >> 3;            // pooled base j0 = 8*pg (0..7)

    for (int i = t; i < 5120; i += 64) {
        int o = i / 160, j = i - o * 160;
        swt[j][o] = Wc2[(oc0 + o) * 160 + j];
    }

    ull acc[4][8];
    #pragma unroll
    for (int oo = 0; oo < 4; oo++)
        #pragma unroll
        for (int j = 0; j < 8; j++) acc[oo][j] = 0ull;

    for (int c = 0; c < 4; c++) {           // ic chunks of 8
        __syncthreads();
        for (int i = t; i < 1056; i += 64) {
            int half = i / 528;             // 0 = e, 1 = o
            int r = i - half * 528;
            int ic = r / 66, j = r - ic * 66;
            int q0 = 2 * (p0 + j) - 2 + half;
            const float* src = g_pool1 + (b * 32 + c * 8 + ic) * 500;
            float v0 = (q0 >= 0 && q0 < 500) ? src[q0] : 0.f;
            int q1 = q0 + 1;
            float v1 = (q1 >= 0 && q1 < 500) ? src[q1] : 0.f;
            if (half == 0) sxe[ic][j] = make_float2(v0, v1);
            else           sxo[ic][j] = make_float2(v0, v1);
        }
        __syncthreads();
        #pragma unroll 2
        for (int i8 = 0; i8 < 8; i8++) {
            int ic = c * 8 + i8;
            ull e[10], o[10];
            const ulonglong2* ep = reinterpret_cast<const ulonglong2*>(&sxe[i8][8 * pg]);
            const ulonglong2* op = reinterpret_cast<const ulonglong2*>(&sxo[i8][8 * pg]);
            #pragma unroll
            for (int q = 0; q < 5; q++) {
                ulonglong2 ve = ep[q]; e[2 * q] = ve.x; e[2 * q + 1] = ve.y;
                ulonglong2 vo = op[q]; o[2 * q] = vo.x; o[2 * q + 1] = vo.y;
            }
            #pragma unroll
            for (int oo = 0; oo < 4; oo++) {
                int ol = 4 * ocg + oo;
                float w0 = swt[ic * 5 + 0][ol];
                float w1 = swt[ic * 5 + 1][ol];
                float w2 = swt[ic * 5 + 2][ol];
                float w3 = swt[ic * 5 + 3][ol];
                float w4 = swt[ic * 5 + 4][ol];
                ull wd0 = pk2(w0, w0), wd1 = pk2(w1, w1), wd2 = pk2(w2, w2);
                ull wd3 = pk2(w3, w3), wd4 = pk2(w4, w4);
                #pragma unroll
                for (int j = 0; j < 8; j++) {
                    ull a = acc[oo][j];
                    a = fma2(e[j],     wd0, a);
                    a = fma2(o[j],     wd1, a);
                    a = fma2(e[j + 1], wd2, a);
                    a = fma2(o[j + 1], wd3, a);
                    a = fma2(e[j + 2], wd4, a);
                    acc[oo][j] = a;
                }
            }
        }
    }

    #pragma unroll
    for (int oo = 0; oo < 4; oo++) {
        int oc = oc0 + 4 * ocg + oo;
        float bb = bc2[oc];
        float gg = gc2[oc] * INV_BN;
        float be = bec2[oc];
        #pragma unroll
        for (int j = 0; j < 8; j++) {
            float2 a = upk2(acc[oo][j]);
            float r = fmaxf(fmaxf(fmaf(a.x + bb, gg, be), fmaf(a.y + bb, gg, be)), 0.f);
            int p = p0 + 8 * pg + j;
            if (p < 250) g_pool2[(b * 64 + oc) * 250 + p] = r;
        }
    }
}

// ---------------------------------------------------------------------------
// K5: conv3 K-split GEMM: part[ks][b][oc] = sum_{k in 32-chunk} X[b][k]*W[oc][k]
// grid 500 K-splits (3.4 blocks/SM -> cross-block latency hiding), 256 threads.
// Staged vectorized loads: 6 LDG.128 per thread (all issued before any STS),
// coalesced 128B groups; W scatter-STS into [kk][oc] (pad 133) conflict-free.
// f32x2 lanes = adjacent batch pair; thread tile 8 b x 4 oc, oc strided 32.
// ---------------------------------------------------------------------------
__global__ void __launch_bounds__(256) k_conv3(const float* __restrict__ Wc3) {
    int ks = blockIdx.x;       // 0..499
    int t = threadIdx.x;
    __shared__ __align__(16) float Xs[32][68];   // [kk][b], pad 68 (16B-aligned rows)
    __shared__ float Ws[32][133];                // [kk][oc], pad 133 (conflict-free)
    int og = t & 31;           // oc = og + 32*o, o=0..3
    int bg = t >> 5;           // warp id -> b0 = 8*bg (x loads warp-broadcast)
    int k0 = ks * 32;

    // ---- staged vector loads: ALL LDG.128 first, then all STS ----
    float4 rw[4], rx[2];
    #pragma unroll
    for (int j = 0; j < 4; j++) {
        int i4 = t + j * 256;
        int oc = i4 >> 3, kq = i4 & 7;
        rw[j] = *reinterpret_cast<const float4*>(Wc3 + oc * 16000 + k0 + 4 * kq);
    }
    #pragma unroll
    for (int j = 0; j < 2; j++) {
        int i4 = t + j * 256;
        int b = i4 >> 3, kq = i4 & 7;
        rx[j] = *reinterpret_cast<const float4*>(g_pool2 + b * 16000 + k0 + 4 * kq);
    }
    #pragma unroll
    for (int j = 0; j < 4; j++) {
        int i4 = t + j * 256;
        int oc = i4 >> 3, kq = i4 & 7;
        Ws[4 * kq + 0][oc] = rw[j].x;
        Ws[4 * kq + 1][oc] = rw[j].y;
        Ws[4 * kq + 2][oc] = rw[j].z;
        Ws[4 * kq + 3][oc] = rw[j].w;
    }
    #pragma unroll
    for (int j = 0; j < 2; j++) {
        int i4 = t + j * 256;
        int b = i4 >> 3, kq = i4 & 7;
        Xs[4 * kq + 0][b] = rx[j].x;
        Xs[4 * kq + 1][b] = rx[j].y;
        Xs[4 * kq + 2][b] = rx[j].z;
        Xs[4 * kq + 3][b] = rx[j].w;
    }
    __syncthreads();

    ull acc[4][4];
    #pragma unroll
    for (int o = 0; o < 4; o++)
        #pragma unroll
        for (int j = 0; j < 4; j++) acc[o][j] = 0ull;

    #pragma unroll 8
    for (int kk = 0; kk < 32; kk++) {
        const ull* xq = reinterpret_cast<const ull*>(&Xs[kk][8 * bg]);
        ull x0 = xq[0], x1 = xq[1], x2 = xq[2], x3 = xq[3];
        #pragma unroll
        for (int o = 0; o < 4; o++) {
            float wv = Ws[kk][og + 32 * o];
            ull wd = pk2(wv, wv);
            acc[o][0] = fma2(x0, wd, acc[o][0]);
            acc[o][1] = fma2(x1, wd, acc[o][1]);
            acc[o][2] = fma2(x2, wd, acc[o][2]);
            acc[o][3] = fma2(x3, wd, acc[o][3]);
        }
    }

    #pragma unroll
    for (int o = 0; o < 4; o++) {
        int oc = og + 32 * o;
        #pragma unroll
        for (int j = 0; j < 4; j++) {
            float2 v = upk2(acc[o][j]);
            int bb = 8 * bg + 2 * j;
            g_part3[(ks * 64 + bb) * 128 + oc]     = v.x;
            g_part3[(ks * 64 + bb + 1) * 128 + oc] = v.y;
        }
    }
}

// ---------------------------------------------------------------------------
// K6: reduce partials (+bc3) with 8-way split-K, FC 128->64 (+bn relu),
// FC 64->12, log_softmax. one block per batch, 1024 threads.
// ---------------------------------------------------------------------------
__global__ void __launch_bounds__(1024) k_fc(
        const float* __restrict__ bc3, const float* __restrict__ Wf,
        const float* __restrict__ bf, const float* __restrict__ gf,
        const float* __restrict__ bef, const float* __restrict__ Wo,
        const float* __restrict__ bo, float* __restrict__ out) {
    int b = blockIdx.x;
    int t = threadIdx.x;
    __shared__ float red[8][128];
    __shared__ float f[128], u[64], o[12];
    {
        int oc = t & 127, r = t >> 7;      // r = 0..7
        float s = 0.f;
        #pragma unroll 7
        for (int ks = r; ks < 500; ks += 8)
            s += g_part3[(ks * 64 + b) * 128 + oc];
        red[r][oc] = s;
    }
    __syncthreads();
    if (t < 128) {
        float s = ((red[0][t] + red[1][t]) + (red[2][t] + red[3][t]))
                + ((red[4][t] + red[5][t]) + (red[6][t] + red[7][t]));
        f[t] = bc3[t] + s;
    }
    __syncthreads();
    if (t < 64) {
        float z = bf[t];
        #pragma unroll 8
        for (int k = 0; k < 128; k++) z = fmaf(f[k], Wf[k * 64 + t], z);
        z = z * (INV_BN * gf[t]) + bef[t];
        u[t] = fmaxf(z, 0.f);
    }
    __syncthreads();
    if (t < 12) {
        float z = bo[t];
        #pragma unroll 8
        for (int k = 0; k < 64; k++) z = fmaf(u[k], Wo[k * 12 + t], z);
        o[t] = z;
    }
    __syncthreads();
    if (t < 12) {
        float m = o[0];
        #pragma unroll
        for (int i = 1; i < 12; i++) m = fmaxf(m, o[i]);
        float s = 0.f;
        #pragma unroll
        for (int i = 0; i < 12; i++) s += expf(o[i] - m);
        out[b * 12 + t] = (o[t] - m) - logf(s);
    }
}

// ---------------------------------------------------------------------------
extern "C" void kernel_launch(void* const* d_in, const int* in_sizes, int n_in,
                              void* d_out, int out_size) {
    const float* x_sample = (const float*)d_in[0];
    const float* x_graph  = (const float*)d_in[1];
    const float* W1   = (const float*)d_in[2];
    const float* b1   = (const float*)d_in[3];
    const float* gl   = (const float*)d_in[4];
    const float* bl   = (const float*)d_in[5];
    const float* Wg   = (const float*)d_in[6];
    const float* bg   = (const float*)d_in[7];
    const float* g1   = (const float*)d_in[8];
    const float* be1  = (const float*)d_in[9];
    const float* Wc1  = (const float*)d_in[10];
    const float* bc1  = (const float*)d_in[11];
    const float* gc1  = (const float*)d_in[12];
    const float* bec1 = (const float*)d_in[13];
    const float* Wc2  = (const float*)d_in[14];
    const float* bc2  = (const float*)d_in[15];
    const float* gc2  = (const float*)d_in[16];
    const float* bec2 = (const float*)d_in[17];
    const float* Wc3  = (const float*)d_in[18];
    const float* bc3  = (const float*)d_in[19];
    const float* Wf   = (const float*)d_in[20];
    const float* bf   = (const float*)d_in[21];
    const float* gf   = (const float*)d_in[22];
    const float* bef  = (const float*)d_in[23];
    const float* Wo   = (const float*)d_in[24];
    const float* bo   = (const float*)d_in[25];
    float* out = (float*)d_out;

    k_front<<<128, 1024>>>(x_sample, W1, b1, gl, bl, x_graph, Wg, bg, g1, be1);
    k_conv1<<<dim3(64, 4), 256>>>(Wc1, bc1, gc1, bec1);
    k_conv2<<<dim3(64, 4, 2), 64>>>(Wc2, bc2, gc2, bec2);
    k_conv3<<<500, 256>>>(Wc3);
    k_fc   <<<64, 1024>>>(bc3, Wf, bf, gf, bef, Wo, bo, out);
}